// round 6
// baseline (speedup 1.0000x reference)
#include <cuda_runtime.h>
#include <cstdint>

#define MAX_NODES 100000
#define MAX_EDGES 1250000
#define HID 64

// Scratch (allocation-free: __device__ globals)
__device__ int    g_cnt[MAX_NODES];       // in-degree (without self loop)
__device__ int    g_rowstart[MAX_NODES];  // CSR row start (exclusive scan of cnt)
__device__ int    g_cursor[MAX_NODES];    // scatter cursors
__device__ int    g_blocksum[256];
__device__ float  g_dinv[MAX_NODES];
__device__ int    g_psrc[MAX_EDGES];      // src ids sorted by dst
__device__ float  g_h[(size_t)MAX_NODES * HID];
__device__ float  g_out1[(size_t)MAX_NODES * HID];
__device__ float2 g_Wh[128 * 32];         // W hi split, B-fragment layout
__device__ float2 g_Wl[128 * 32];         // W lo split

// ---------------------------------------------------------------------------
// CSR build: count -> scan(3 kernels) -> finish(dinv+cursor) -> scatter
// ---------------------------------------------------------------------------
__global__ void k_zero_cnt(int n) {
    int i = blockIdx.x * blockDim.x + threadIdx.x;
    if (i < n) g_cnt[i] = 0;
}

__global__ void k_count(const int* __restrict__ dst, int nE) {
    int e = blockIdx.x * blockDim.x + threadIdx.x;
    if (e < nE) atomicAdd(&g_cnt[__ldg(&dst[e])], 1);
}

__global__ void __launch_bounds__(1024) k_scan_block(int n) {
    __shared__ int sh[1024];
    const int t = threadIdx.x;
    const int i = blockIdx.x * 1024 + t;
    int v = (i < n) ? g_cnt[i] : 0;
    sh[t] = v;
    __syncthreads();
#pragma unroll
    for (int off = 1; off < 1024; off <<= 1) {
        int add = (t >= off) ? sh[t - off] : 0;
        __syncthreads();
        sh[t] += add;
        __syncthreads();
    }
    if (i < n) g_rowstart[i] = sh[t] - v;
    if (t == 1023) g_blocksum[blockIdx.x] = sh[t];
}

__global__ void __launch_bounds__(128) k_scan_tops(int nb) {
    __shared__ int sh[128];
    const int t = threadIdx.x;
    int v = (t < nb) ? g_blocksum[t] : 0;
    sh[t] = v;
    __syncthreads();
#pragma unroll
    for (int off = 1; off < 128; off <<= 1) {
        int add = (t >= off) ? sh[t - off] : 0;
        __syncthreads();
        sh[t] += add;
        __syncthreads();
    }
    if (t < nb) g_blocksum[t] = sh[t] - v;
}

__global__ void k_scan_finish(int n) {
    int i = blockIdx.x * blockDim.x + threadIdx.x;
    if (i < n) {
        int rs = g_rowstart[i] + g_blocksum[i >> 10];
        g_rowstart[i] = rs;
        g_cursor[i]   = rs;
        g_dinv[i]     = rsqrtf((float)g_cnt[i] + 1.0f);
    }
}

__global__ void k_scatter(const int* __restrict__ src, const int* __restrict__ dst, int nE) {
    int e = blockIdx.x * blockDim.x + threadIdx.x;
    if (e < nE) {
        int d = __ldg(&dst[e]);
        int pos = atomicAdd(&g_cursor[d], 1);
        g_psrc[pos] = __ldg(&src[e]);
    }
}

// ---------------------------------------------------------------------------
// tf32 helpers
// ---------------------------------------------------------------------------
__device__ __forceinline__ void tf32_split(float f, uint32_t& hi, uint32_t& lo) {
    uint32_t h;
    asm("cvt.rna.tf32.f32 %0, %1;" : "=r"(h) : "f"(f));
    float r = f - __uint_as_float(h);
    uint32_t l;
    asm("cvt.rna.tf32.f32 %0, %1;" : "=r"(l) : "f"(r));
    hi = h; lo = l;
}

__device__ __forceinline__ void mma_tf32(float* c,
                                         uint32_t a0, uint32_t a1, uint32_t a2, uint32_t a3,
                                         uint32_t b0, uint32_t b1) {
    asm volatile("mma.sync.aligned.m16n8k8.row.col.f32.tf32.tf32.f32 "
                 "{%0,%1,%2,%3}, {%4,%5,%6,%7}, {%8,%9}, {%0,%1,%2,%3};"
                 : "+f"(c[0]), "+f"(c[1]), "+f"(c[2]), "+f"(c[3])
                 : "r"(a0), "r"(a1), "r"(a2), "r"(a3), "r"(b0), "r"(b1));
}

// Pre-split W [KDIM x 64] into B-fragment layout:
//  idx = (kstep*8 + ntile)*32 + lane ; element pair (k = kstep*8 + lane%4 (+4), n = ntile*8 + lane/4)
__global__ void k_split_w(const float* __restrict__ W, int KDIM) {
    int idx = blockIdx.x * blockDim.x + threadIdx.x;
    int total = (KDIM >> 3) * 8 * 32;
    if (idx >= total) return;
    int lane = idx & 31;
    int nt   = (idx >> 5) & 7;
    int ks   = idx >> 8;
    int k = ks * 8 + (lane & 3);
    int n = nt * 8 + (lane >> 2);
    float w0 = __ldg(&W[k * 64 + n]);
    float w1 = __ldg(&W[(k + 4) * 64 + n]);
    uint32_t h0, l0, h1, l1;
    tf32_split(w0, h0, l0);
    tf32_split(w1, h1, l1);
    g_Wh[idx] = make_float2(__uint_as_float(h0), __uint_as_float(h1));
    g_Wl[idx] = make_float2(__uint_as_float(l0), __uint_as_float(l1));
}

// ---------------------------------------------------------------------------
// Tensor-core GEMM: h = act(A) @ W  [M x KDIM] @ [KDIM x 64], tf32x3 split.
// Epilogue: hout = h ; aout = bias + h * dinv^2.
// CTA: 128 rows x 64 cols, 8 warps (warp w: rows 16w..16w+15).
// ---------------------------------------------------------------------------
#define AS_STRIDE 36
#define AS_BYTES (128 * AS_STRIDE * 4)

template<int KDIM, bool RELU_IN>
__global__ void __launch_bounds__(256) k_gemm_tc(const float* __restrict__ A,
                                                 const float* __restrict__ bias,
                                                 float* __restrict__ hout,
                                                 float* __restrict__ aout,
                                                 int M)
{
    extern __shared__ char smem[];
    float*  As  = reinterpret_cast<float*>(smem);                       // [128][36]
    float2* Whs = reinterpret_cast<float2*>(smem + AS_BYTES);           // KDIM*32
    float2* Wls = Whs + KDIM * 32;

    const int tid  = threadIdx.x;
    const int lane = tid & 31;
    const int warp = tid >> 5;
    const int row0 = blockIdx.x * 128;

    // Load pre-split W fragments into smem (linear copy)
    for (int i = tid; i < KDIM * 32; i += 256) {
        Whs[i] = g_Wh[i];
        Wls[i] = g_Wl[i];
    }

    float acc[8][4];
#pragma unroll
    for (int nt = 0; nt < 8; nt++)
#pragma unroll
        for (int j = 0; j < 4; j++) acc[nt][j] = 0.0f;

    const int lrow = tid >> 1;                 // 0..127
    const int lcol = (tid & 1) * 16;           // 0 or 16
    const int arow = min(row0 + lrow, M - 1);
    const int r  = lane >> 2;
    const int kk = lane & 3;

    for (int k0 = 0; k0 < KDIM; k0 += 32) {
        // Cooperative A chunk load: 128 rows x 32 cols
#pragma unroll
        for (int i = 0; i < 4; i++) {
            float4 av = *reinterpret_cast<const float4*>(A + (size_t)arow * KDIM + k0 + lcol + i * 4);
            if (RELU_IN) {
                av.x = fmaxf(av.x, 0.0f); av.y = fmaxf(av.y, 0.0f);
                av.z = fmaxf(av.z, 0.0f); av.w = fmaxf(av.w, 0.0f);
            }
            float* p = As + lrow * AS_STRIDE + lcol + i * 4;
            p[0] = av.x; p[1] = av.y; p[2] = av.z; p[3] = av.w;
        }
        __syncthreads();

#pragma unroll
        for (int ks = 0; ks < 4; ks++) {
            const int kb = ks * 8;
            const float* ap = As + (warp * 16 + r) * AS_STRIDE + kb + kk;
            float f0 = ap[0];
            float f1 = ap[8 * AS_STRIDE];
            float f2 = ap[4];
            float f3 = ap[8 * AS_STRIDE + 4];
            uint32_t ah0, al0, ah1, al1, ah2, al2, ah3, al3;
            tf32_split(f0, ah0, al0);
            tf32_split(f1, ah1, al1);
            tf32_split(f2, ah2, al2);
            tf32_split(f3, ah3, al3);

            const int wbase = (((k0 >> 3) + ks) * 8) * 32 + lane;
#pragma unroll
            for (int nt = 0; nt < 8; nt++) {
                float2 bh = Whs[wbase + nt * 32];
                float2 bl = Wls[wbase + nt * 32];
                uint32_t bh0 = __float_as_uint(bh.x), bh1 = __float_as_uint(bh.y);
                uint32_t bl0 = __float_as_uint(bl.x), bl1 = __float_as_uint(bl.y);
                mma_tf32(acc[nt], ah0, ah1, ah2, ah3, bh0, bh1);  // hi*hi
                mma_tf32(acc[nt], ah0, ah1, ah2, ah3, bl0, bl1);  // hi*lo
                mma_tf32(acc[nt], al0, al1, al2, al3, bh0, bh1);  // lo*hi
            }
        }
        __syncthreads();
    }

    // Epilogue from C fragments: c0,c1 -> (row, 2c), (row, 2c+1); c2,c3 -> row+8
    const int col0 = (lane & 3) * 2;
    const int mr0  = row0 + warp * 16 + r;
    const int mr1  = mr0 + 8;
    const float dv0 = (mr0 < M) ? g_dinv[mr0] : 0.0f;
    const float dv1 = (mr1 < M) ? g_dinv[mr1] : 0.0f;
    const float d20 = dv0 * dv0, d21 = dv1 * dv1;

#pragma unroll
    for (int nt = 0; nt < 8; nt++) {
        const int col = nt * 8 + col0;
        const float2 bv = *reinterpret_cast<const float2*>(bias + col);
        if (mr0 < M) {
            *reinterpret_cast<float2*>(hout + (size_t)mr0 * HID + col) =
                make_float2(acc[nt][0], acc[nt][1]);
            *reinterpret_cast<float2*>(aout + (size_t)mr0 * HID + col) =
                make_float2(bv.x + acc[nt][0] * d20, bv.y + acc[nt][1] * d20);
        }
        if (mr1 < M) {
            *reinterpret_cast<float2*>(hout + (size_t)mr1 * HID + col) =
                make_float2(acc[nt][2], acc[nt][3]);
            *reinterpret_cast<float2*>(aout + (size_t)mr1 * HID + col) =
                make_float2(bv.x + acc[nt][2] * d21, bv.y + acc[nt][3] * d21);
        }
    }
}

// ---------------------------------------------------------------------------
// Pull-mode aggregation over CSR: out[d] += dinv[d] * sum_{s in N(d)} dinv[s]*h[s]
// ---------------------------------------------------------------------------
__global__ void __launch_bounds__(256) k_node_agg(const float* __restrict__ h,
                                                   float* __restrict__ out,
                                                   int n)
{
    const int gid  = blockIdx.x * blockDim.x + threadIdx.x;
    const int node = gid >> 4;
    const int l    = gid & 15;
    if (node >= n) return;

    const int start = __ldg(&g_rowstart[node]);
    const int cn    = __ldg(&g_cnt[node]);
    const int half  = cn >> 1;

    float4 acc0 = make_float4(0.f, 0.f, 0.f, 0.f);
    float4 acc1 = make_float4(0.f, 0.f, 0.f, 0.f);

    const int a0 = start;
    const int b0 = start + half;
    for (int k = 0; k < half; k++) {
        const int sa = __ldg(&g_psrc[a0 + k]);
        const int sb = __ldg(&g_psrc[b0 + k]);
        const float wa = __ldg(&g_dinv[sa]);
        const float wb = __ldg(&g_dinv[sb]);
        const float4 va = __ldg(reinterpret_cast<const float4*>(h + (size_t)sa * HID) + l);
        const float4 vb = __ldg(reinterpret_cast<const float4*>(h + (size_t)sb * HID) + l);
        acc0.x = fmaf(wa, va.x, acc0.x); acc1.x = fmaf(wb, vb.x, acc1.x);
        acc0.y = fmaf(wa, va.y, acc0.y); acc1.y = fmaf(wb, vb.y, acc1.y);
        acc0.z = fmaf(wa, va.z, acc0.z); acc1.z = fmaf(wb, vb.z, acc1.z);
        acc0.w = fmaf(wa, va.w, acc0.w); acc1.w = fmaf(wb, vb.w, acc1.w);
    }
    if (cn & 1) {
        const int s = __ldg(&g_psrc[start + cn - 1]);
        const float w = __ldg(&g_dinv[s]);
        const float4 v = __ldg(reinterpret_cast<const float4*>(h + (size_t)s * HID) + l);
        acc0.x = fmaf(w, v.x, acc0.x);
        acc0.y = fmaf(w, v.y, acc0.y);
        acc0.z = fmaf(w, v.z, acc0.z);
        acc0.w = fmaf(w, v.w, acc0.w);
    }

    const float dd = __ldg(&g_dinv[node]);
    float* p = out + (size_t)node * HID + l * 4;
    float4 o = *reinterpret_cast<float4*>(p);
    o.x += dd * (acc0.x + acc1.x);
    o.y += dd * (acc0.y + acc1.y);
    o.z += dd * (acc0.z + acc1.z);
    o.w += dd * (acc0.w + acc1.w);
    *reinterpret_cast<float4*>(p) = o;
}

// ---------------------------------------------------------------------------
// Launch
// ---------------------------------------------------------------------------
extern "C" void kernel_launch(void* const* d_in, const int* in_sizes, int n_in,
                              void* d_out, int out_size)
{
    const float* x  = (const float*)d_in[0];
    const int*   ei = (const int*)d_in[1];   // edge_index is int32
    const float* W1 = (const float*)d_in[2];
    const float* b1 = (const float*)d_in[3];
    const float* W2 = (const float*)d_in[4];
    const float* b2 = (const float*)d_in[5];
    float* out = (float*)d_out;

    const int n  = in_sizes[0] / 128;
    const int nE = in_sizes[1] / 2;
    const int* src = ei;
    const int* dst = ei + nE;

    float *h = nullptr, *out1 = nullptr;
    cudaGetSymbolAddress((void**)&h, g_h);
    cudaGetSymbolAddress((void**)&out1, g_out1);

    const int nb_nodes = (n + 255) / 256;
    const int nb_edges = (nE + 255) / 256;
    const int nb_scan  = (n + 1023) / 1024;
    const int nb_agg   = (n * 16 + 255) / 256;
    const int nb_gemm  = (n + 127) / 128;

    const int smem1 = AS_BYTES + 128 * 32 * 2 * (int)sizeof(float2);  // 83968
    const int smem2 = AS_BYTES + 64 * 32 * 2 * (int)sizeof(float2);   // 51200
    cudaFuncSetAttribute(k_gemm_tc<128, false>, cudaFuncAttributeMaxDynamicSharedMemorySize, smem1);
    cudaFuncSetAttribute(k_gemm_tc<64, true>,   cudaFuncAttributeMaxDynamicSharedMemorySize, smem2);

    // CSR build + dinv
    k_zero_cnt<<<nb_nodes, 256>>>(n);
    k_count<<<nb_edges, 256>>>(dst, nE);
    k_scan_block<<<nb_scan, 1024>>>(n);
    k_scan_tops<<<1, 128>>>(nb_scan);
    k_scan_finish<<<nb_nodes, 256>>>(n);
    k_scatter<<<nb_edges, 256>>>(src, dst, nE);

    // Layer 1
    k_split_w<<<(128 * 32 + 255) / 256, 256>>>(W1, 128);
    k_gemm_tc<128, false><<<nb_gemm, 256, smem1>>>(x, b1, h, out1, n);
    k_node_agg<<<nb_agg, 256>>>(h, out1, n);

    // Layer 2 (ReLU fused into A-load; init written straight to d_out)
    k_split_w<<<(64 * 32 + 255) / 256, 256>>>(W2, 64);
    k_gemm_tc<64, true><<<nb_gemm, 256, smem2>>>(out1, b2, h, out, n);
    k_node_agg<<<nb_agg, 256>>>(h, out, n);
}

// round 7
// speedup vs baseline: 1.0830x; 1.0830x over previous
#include <cuda_runtime.h>
#include <cuda_fp16.h>
#include <cstdint>

#define MAX_NODES 100000
#define MAX_EDGES 1250000
#define HID 64

// Scratch (allocation-free: __device__ globals)
__device__ int     g_cnt[MAX_NODES];       // in-degree (without self loop)
__device__ int     g_rowstart[MAX_NODES];  // CSR row start
__device__ int     g_cursor[MAX_NODES];    // scatter cursors
__device__ int     g_blocksum[256];        // per-1024-segment totals
__device__ float   g_dinv[MAX_NODES];
__device__ int     g_psrc[MAX_EDGES];      // src ids sorted by dst
__device__ __half2 g_hh[(size_t)MAX_NODES * (HID / 2)];  // dinv[s]*h[s], fp16
__device__ float   g_out1[(size_t)MAX_NODES * HID];      // layer-1 output

// ---------------------------------------------------------------------------
// CSR build: zero -> count -> block scan -> finish(+tops reduce) -> scatter
// ---------------------------------------------------------------------------
__global__ void k_zero_cnt(int n) {
    int i = blockIdx.x * blockDim.x + threadIdx.x;
    if (i < n) g_cnt[i] = 0;
}

__global__ void k_count(const int* __restrict__ dst, int nE) {
    int e = blockIdx.x * blockDim.x + threadIdx.x;
    if (e < nE) atomicAdd(&g_cnt[__ldg(&dst[e])], 1);
}

__global__ void __launch_bounds__(1024) k_scan_block(int n) {
    __shared__ int sh[1024];
    const int t = threadIdx.x;
    const int i = blockIdx.x * 1024 + t;
    int v = (i < n) ? g_cnt[i] : 0;
    sh[t] = v;
    __syncthreads();
#pragma unroll
    for (int off = 1; off < 1024; off <<= 1) {
        int add = (t >= off) ? sh[t - off] : 0;
        __syncthreads();
        sh[t] += add;
        __syncthreads();
    }
    if (i < n) g_rowstart[i] = sh[t] - v;            // exclusive within segment
    if (t == 1023) g_blocksum[blockIdx.x] = sh[t];   // segment total
}

// Adds the prefix of segment totals (reduced in-block), computes cursor + dinv.
__global__ void __launch_bounds__(256) k_scan_finish(int n) {
    __shared__ int sh[128];
    const int t = threadIdx.x;
    const int seg = blockIdx.x >> 2;        // this block's 1024-node segment
    if (t < 128) sh[t] = (t < seg) ? g_blocksum[t] : 0;
    __syncthreads();
#pragma unroll
    for (int off = 64; off > 0; off >>= 1) {
        if (t < off) sh[t] += sh[t + off];
        __syncthreads();
    }
    const int base = sh[0];
    const int i = blockIdx.x * 256 + t;
    if (i < n) {
        int rs = g_rowstart[i] + base;
        g_rowstart[i] = rs;
        g_cursor[i]   = rs;
        g_dinv[i]     = rsqrtf((float)g_cnt[i] + 1.0f);  // +1 self loop
    }
}

__global__ void k_scatter(const int* __restrict__ src, const int* __restrict__ dst, int nE) {
    int e = blockIdx.x * blockDim.x + threadIdx.x;
    if (e < nE) {
        int d = __ldg(&dst[e]);
        int pos = atomicAdd(&g_cursor[d], 1);
        g_psrc[pos] = __ldg(&src[e]);
    }
}

// ---------------------------------------------------------------------------
// GEMM: h = act(A) @ W  [M x KDIM] @ [KDIM x 64]
// Epilogue: hh = fp16(h * dinv)  (pre-scaled gather table)
//           aout = bias + (h*dinv) * dinv   (self-loop + bias folded in)
// Block tile 128x64, 256 threads, 8x4 register tile, BK=8. (R5 SIMT version)
// ---------------------------------------------------------------------------
template<int KDIM, bool RELU_IN>
__global__ void __launch_bounds__(256) k_gemm(const float* __restrict__ A,
                                              const float* __restrict__ W,
                                              const float* __restrict__ bias,
                                              __half2* __restrict__ hout,
                                              float* __restrict__ aout,
                                              int M)
{
    __shared__ float As[8][128];
    __shared__ float Bs[8][64];

    const int tx = threadIdx.x & 15;
    const int ty = threadIdx.x >> 4;
    const int row0 = blockIdx.x * 128;

    float acc[8][4];
#pragma unroll
    for (int i = 0; i < 8; i++)
#pragma unroll
        for (int j = 0; j < 4; j++) acc[i][j] = 0.0f;

    const int lrow = threadIdx.x >> 1;
    const int lcol = (threadIdx.x & 1) * 4;
    const int arow = min(row0 + lrow, M - 1);

    for (int k0 = 0; k0 < KDIM; k0 += 8) {
        float4 av = *reinterpret_cast<const float4*>(A + (size_t)arow * KDIM + k0 + lcol);
        if (RELU_IN) {
            av.x = fmaxf(av.x, 0.0f); av.y = fmaxf(av.y, 0.0f);
            av.z = fmaxf(av.z, 0.0f); av.w = fmaxf(av.w, 0.0f);
        }
        As[lcol + 0][lrow] = av.x;
        As[lcol + 1][lrow] = av.y;
        As[lcol + 2][lrow] = av.z;
        As[lcol + 3][lrow] = av.w;
        if (threadIdx.x < 128) {
            const int bk = threadIdx.x >> 4;
            const int bj = (threadIdx.x & 15) * 4;
            *reinterpret_cast<float4*>(&Bs[bk][bj]) =
                *reinterpret_cast<const float4*>(W + (size_t)(k0 + bk) * HID + bj);
        }
        __syncthreads();
#pragma unroll
        for (int kk = 0; kk < 8; kk++) {
            float4 a0 = *reinterpret_cast<const float4*>(&As[kk][ty * 8]);
            float4 a1 = *reinterpret_cast<const float4*>(&As[kk][ty * 8 + 4]);
            float4 bv = *reinterpret_cast<const float4*>(&Bs[kk][tx * 4]);
            float a[8] = {a0.x, a0.y, a0.z, a0.w, a1.x, a1.y, a1.z, a1.w};
            float b[4] = {bv.x, bv.y, bv.z, bv.w};
#pragma unroll
            for (int i = 0; i < 8; i++)
#pragma unroll
                for (int j = 0; j < 4; j++) acc[i][j] = fmaf(a[i], b[j], acc[i][j]);
        }
        __syncthreads();
    }

    const float4 bvv = *reinterpret_cast<const float4*>(bias + tx * 4);
#pragma unroll
    for (int i = 0; i < 8; i++) {
        const int m = row0 + ty * 8 + i;
        if (m < M) {
            const float dv = g_dinv[m];
            // pre-scaled values: hs = h * dinv[m]
            const float hs0 = acc[i][0] * dv, hs1 = acc[i][1] * dv;
            const float hs2 = acc[i][2] * dv, hs3 = acc[i][3] * dv;
            // fp16 gather table (row = 32 half2, lane covers 2 half2)
            __half2 p0 = __floats2half2_rn(hs0, hs1);
            __half2 p1 = __floats2half2_rn(hs2, hs3);
            __half2* hp = hout + (size_t)m * (HID / 2) + tx * 2;
            hp[0] = p0; hp[1] = p1;
            // aggregation init: bias + hs * dinv (fp32 precision)
            float4 ov = make_float4(bvv.x + hs0 * dv, bvv.y + hs1 * dv,
                                    bvv.z + hs2 * dv, bvv.w + hs3 * dv);
            *reinterpret_cast<float4*>(aout + (size_t)m * HID + tx * 4) = ov;
        }
    }
}

// ---------------------------------------------------------------------------
// Pull-mode aggregation over CSR: out[d] += dinv[d] * sum_{s in N(d)} hh[s]
// (hh already holds dinv[s]*h[s] in fp16.) 8 lanes per dst node; each lane
// gathers 16B (4 half2) per edge; two independent chains for MLP.
// ---------------------------------------------------------------------------
__device__ __forceinline__ void acc_16B(float2* acc, uint4 v) {
    float2 f0 = __half22float2(*reinterpret_cast<__half2*>(&v.x));
    float2 f1 = __half22float2(*reinterpret_cast<__half2*>(&v.y));
    float2 f2 = __half22float2(*reinterpret_cast<__half2*>(&v.z));
    float2 f3 = __half22float2(*reinterpret_cast<__half2*>(&v.w));
    acc[0].x += f0.x; acc[0].y += f0.y;
    acc[1].x += f1.x; acc[1].y += f1.y;
    acc[2].x += f2.x; acc[2].y += f2.y;
    acc[3].x += f3.x; acc[3].y += f3.y;
}

__global__ void __launch_bounds__(256) k_node_agg(const __half2* __restrict__ hh,
                                                  float* __restrict__ out,
                                                  int n)
{
    const int gid  = blockIdx.x * blockDim.x + threadIdx.x;
    const int node = gid >> 3;
    const int l    = gid & 7;              // 16B chunk within the 128B row
    if (node >= n) return;

    const int start = __ldg(&g_rowstart[node]);
    const int cn    = __ldg(&g_cnt[node]);
    const int half  = cn >> 1;

    float2 accA[4] = {{0,0},{0,0},{0,0},{0,0}};
    float2 accB[4] = {{0,0},{0,0},{0,0},{0,0}};

    const int a0 = start;
    const int b0 = start + half;
    for (int k = 0; k < half; k++) {
        const int sa = __ldg(&g_psrc[a0 + k]);
        const int sb = __ldg(&g_psrc[b0 + k]);
        const uint4 va = __ldg(reinterpret_cast<const uint4*>(hh + (size_t)sa * (HID / 2)) + l);
        const uint4 vb = __ldg(reinterpret_cast<const uint4*>(hh + (size_t)sb * (HID / 2)) + l);
        acc_16B(accA, va);
        acc_16B(accB, vb);
    }
    if (cn & 1) {
        const int s = __ldg(&g_psrc[start + cn - 1]);
        const uint4 v = __ldg(reinterpret_cast<const uint4*>(hh + (size_t)s * (HID / 2)) + l);
        acc_16B(accA, v);
    }

    const float dd = __ldg(&g_dinv[node]);
    float* p = out + (size_t)node * HID + l * 8;
    float4 o0 = *reinterpret_cast<float4*>(p);
    float4 o1 = *reinterpret_cast<float4*>(p + 4);
    o0.x += dd * (accA[0].x + accB[0].x);
    o0.y += dd * (accA[0].y + accB[0].y);
    o0.z += dd * (accA[1].x + accB[1].x);
    o0.w += dd * (accA[1].y + accB[1].y);
    o1.x += dd * (accA[2].x + accB[2].x);
    o1.y += dd * (accA[2].y + accB[2].y);
    o1.z += dd * (accA[3].x + accB[3].x);
    o1.w += dd * (accA[3].y + accB[3].y);
    *reinterpret_cast<float4*>(p)     = o0;
    *reinterpret_cast<float4*>(p + 4) = o1;
}

// ---------------------------------------------------------------------------
// Launch
// ---------------------------------------------------------------------------
extern "C" void kernel_launch(void* const* d_in, const int* in_sizes, int n_in,
                              void* d_out, int out_size)
{
    const float* x  = (const float*)d_in[0];
    const int*   ei = (const int*)d_in[1];   // edge_index is int32
    const float* W1 = (const float*)d_in[2];
    const float* b1 = (const float*)d_in[3];
    const float* W2 = (const float*)d_in[4];
    const float* b2 = (const float*)d_in[5];
    float* out = (float*)d_out;

    const int n  = in_sizes[0] / 128;
    const int nE = in_sizes[1] / 2;
    const int* src = ei;
    const int* dst = ei + nE;

    __half2* hh = nullptr;
    float* out1 = nullptr;
    cudaGetSymbolAddress((void**)&hh, g_hh);
    cudaGetSymbolAddress((void**)&out1, g_out1);

    const int nb_nodes = (n + 255) / 256;
    const int nb_edges = (nE + 255) / 256;
    const int nb_scan  = (n + 1023) / 1024;
    const int nb_agg   = (n * 8 + 255) / 256;
    const int nb_gemm  = (n + 127) / 128;

    // CSR build + dinv (5 kernels)
    k_zero_cnt<<<nb_nodes, 256>>>(n);
    k_count<<<nb_edges, 256>>>(dst, nE);
    k_scan_block<<<nb_scan, 1024>>>(n);
    k_scan_finish<<<nb_nodes, 256>>>(n);
    k_scatter<<<nb_edges, 256>>>(src, dst, nE);

    // Layer 1
    k_gemm<128, false><<<nb_gemm, 256>>>(x, W1, b1, hh, out1, n);
    k_node_agg<<<nb_agg, 256>>>(hh, out1, n);

    // Layer 2 (ReLU fused into A-load; init written straight to d_out)
    k_gemm<64, true><<<nb_gemm, 256>>>(out1, W2, b2, hh, out, n);
    k_node_agg<<<nb_agg, 256>>>(hh, out, n);
}

// round 9
// speedup vs baseline: 1.2559x; 1.1597x over previous
#include <cuda_runtime.h>
#include <cuda_fp16.h>
#include <cstdint>

#define MAX_NODES 100000
#define MAX_EDGES 1250000
#define HID 64

// Scratch (allocation-free: __device__ globals)
__device__ int     g_cnt[MAX_NODES];
__device__ int     g_rowstart[MAX_NODES];
__device__ int     g_cursor[MAX_NODES];
__device__ int     g_blocksum[256];
__device__ float   g_dinv[MAX_NODES];
__device__ int     g_psrc[MAX_EDGES];
__device__ __half2 g_hh[(size_t)MAX_NODES * (HID / 2)];  // dinv[s]*h[s], fp16
__device__ float   g_out1[(size_t)MAX_NODES * HID];
__device__ uint2   g_Wf1[8 * 8 * 32];   // W1 fragments: (K=128)/16 ksteps x 8 ntiles x 32 lanes
__device__ uint2   g_Wf2[4 * 8 * 32];   // W2 fragments: (K=64)/16 x 8 x 32

// ---------------------------------------------------------------------------
// CSR build: zero -> count -> block scan -> finish -> scatter
// ---------------------------------------------------------------------------
__global__ void k_zero_cnt(int n) {
    int i = blockIdx.x * blockDim.x + threadIdx.x;
    if (i < n) g_cnt[i] = 0;
}

__global__ void k_count(const int* __restrict__ dst, int nE) {
    int e = blockIdx.x * blockDim.x + threadIdx.x;
    if (e < nE) atomicAdd(&g_cnt[__ldg(&dst[e])], 1);
}

__global__ void __launch_bounds__(1024) k_scan_block(int n) {
    __shared__ int sh[1024];
    const int t = threadIdx.x;
    const int i = blockIdx.x * 1024 + t;
    int v = (i < n) ? g_cnt[i] : 0;
    sh[t] = v;
    __syncthreads();
#pragma unroll
    for (int off = 1; off < 1024; off <<= 1) {
        int add = (t >= off) ? sh[t - off] : 0;
        __syncthreads();
        sh[t] += add;
        __syncthreads();
    }
    if (i < n) g_rowstart[i] = sh[t] - v;
    if (t == 1023) g_blocksum[blockIdx.x] = sh[t];
}

__global__ void __launch_bounds__(256) k_scan_finish(int n) {
    __shared__ int sh[128];
    const int t = threadIdx.x;
    const int seg = blockIdx.x >> 2;
    if (t < 128) sh[t] = (t < seg) ? g_blocksum[t] : 0;
    __syncthreads();
#pragma unroll
    for (int off = 64; off > 0; off >>= 1) {
        if (t < off) sh[t] += sh[t + off];
        __syncthreads();
    }
    const int base = sh[0];
    const int i = blockIdx.x * 256 + t;
    if (i < n) {
        int rs = g_rowstart[i] + base;
        g_rowstart[i] = rs;
        g_cursor[i]   = rs;
        g_dinv[i]     = rsqrtf((float)g_cnt[i] + 1.0f);
    }
}

__global__ void k_scatter(const int* __restrict__ src, const int* __restrict__ dst, int nE) {
    int e = blockIdx.x * blockDim.x + threadIdx.x;
    if (e < nE) {
        int d = __ldg(&dst[e]);
        int pos = atomicAdd(&g_cursor[d], 1);
        g_psrc[pos] = __ldg(&src[e]);
    }
}

// ---------------------------------------------------------------------------
// Pack W1 [128x64] and W2 [64x64] into m16n8k16 B-fragment layout (fp16).
// rel = (kstep*8 + nt)*32 + lane ; b0 = W[k0+2c +0/1][n], b1 = W[k0+2c+8 +0/1][n]
// with c = lane&3, n = nt*8 + lane>>2, k0 = kstep*16.
// ---------------------------------------------------------------------------
__global__ void k_pack_w(const float* __restrict__ W1, const float* __restrict__ W2) {
    int idx = blockIdx.x * blockDim.x + threadIdx.x;
    const float* W;
    uint2* dstf;
    int rel;
    if (idx < 2048)      { W = W1; dstf = g_Wf1; rel = idx; }
    else if (idx < 3072) { W = W2; dstf = g_Wf2; rel = idx - 2048; }
    else return;
    const int lane  = rel & 31;
    const int nt    = (rel >> 5) & 7;
    const int kstep = rel >> 8;
    const int nn = nt * 8 + (lane >> 2);
    const int k0 = kstep * 16 + (lane & 3) * 2;
    __half2 b0 = __floats2half2_rn(__ldg(&W[(size_t)k0 * 64 + nn]),
                                   __ldg(&W[(size_t)(k0 + 1) * 64 + nn]));
    __half2 b1 = __floats2half2_rn(__ldg(&W[(size_t)(k0 + 8) * 64 + nn]),
                                   __ldg(&W[(size_t)(k0 + 9) * 64 + nn]));
    uint2 u;
    u.x = *reinterpret_cast<uint32_t*>(&b0);
    u.y = *reinterpret_cast<uint32_t*>(&b1);
    dstf[rel] = u;
}

// ---------------------------------------------------------------------------
// fp16 HMMA GEMM: h = act(A) @ W  [M x KDIM] @ [KDIM x 64]
// mma.sync.m16n8k16.f32.f16.f16.f32, fp32 accumulators.
// CTA: 128 rows x 64 cols, 8 warps (warp w: rows 16w..16w+15).
// Epilogue: hh = fp16(h*dinv) ; aout = bias + (h*dinv)*dinv.
// ---------------------------------------------------------------------------
#define ASTR 136   // halves per A row in smem (conflict-free fragment loads)

__device__ __forceinline__ void mma_f16(float* c,
                                        uint32_t a0, uint32_t a1, uint32_t a2, uint32_t a3,
                                        uint32_t b0, uint32_t b1) {
    asm volatile("mma.sync.aligned.m16n8k16.row.col.f32.f16.f16.f32 "
                 "{%0,%1,%2,%3}, {%4,%5,%6,%7}, {%8,%9}, {%0,%1,%2,%3};"
                 : "+f"(c[0]), "+f"(c[1]), "+f"(c[2]), "+f"(c[3])
                 : "r"(a0), "r"(a1), "r"(a2), "r"(a3), "r"(b0), "r"(b1));
}

template<int KDIM, bool RELU_IN>
__global__ void __launch_bounds__(256) k_gemm_hmma(const float* __restrict__ A,
                                                   const uint2* __restrict__ Wf,
                                                   const float* __restrict__ bias,
                                                   __half2* __restrict__ hout,
                                                   float* __restrict__ aout,
                                                   int M)
{
    extern __shared__ char smem[];
    __half* As = reinterpret_cast<__half*>(smem);                     // 128 x ASTR halves
    uint2*  Bf = reinterpret_cast<uint2*>(smem + 128 * ASTR * 2);     // (KDIM/16)*256

    const int tid  = threadIdx.x;
    const int lane = tid & 31;
    const int warp = tid >> 5;
    const int row0 = blockIdx.x * 128;

    // B fragments -> smem (linear)
    for (int i = tid; i < (KDIM / 16) * 256; i += 256) Bf[i] = Wf[i];

    // A tile fp32 -> fp16 smem
    const int lrow = tid >> 1;
    const int lc4  = (tid & 1) * 4;
    const int arow = min(row0 + lrow, M - 1);
#pragma unroll
    for (int k0 = 0; k0 < KDIM; k0 += 8) {
        float4 av = *reinterpret_cast<const float4*>(A + (size_t)arow * KDIM + k0 + lc4);
        if (RELU_IN) {
            av.x = fmaxf(av.x, 0.0f); av.y = fmaxf(av.y, 0.0f);
            av.z = fmaxf(av.z, 0.0f); av.w = fmaxf(av.w, 0.0f);
        }
        __half2 h0 = __floats2half2_rn(av.x, av.y);
        __half2 h1 = __floats2half2_rn(av.z, av.w);
        uint2 u;
        u.x = *reinterpret_cast<uint32_t*>(&h0);
        u.y = *reinterpret_cast<uint32_t*>(&h1);
        *reinterpret_cast<uint2*>(As + lrow * ASTR + k0 + lc4) = u;
    }
    __syncthreads();

    float acc[8][4];
#pragma unroll
    for (int nt = 0; nt < 8; nt++)
#pragma unroll
        for (int j = 0; j < 4; j++) acc[nt][j] = 0.0f;

    const int r  = lane >> 2;
    const int c2 = (lane & 3) * 2;
    const __half* abase = As + (warp * 16 + r) * ASTR + c2;

#pragma unroll
    for (int ks = 0; ks < KDIM / 16; ks++) {
        const int k0 = ks * 16;
        uint32_t a0 = *reinterpret_cast<const uint32_t*>(abase + k0);
        uint32_t a1 = *reinterpret_cast<const uint32_t*>(abase + k0 + 8 * ASTR);
        uint32_t a2 = *reinterpret_cast<const uint32_t*>(abase + k0 + 8);
        uint32_t a3 = *reinterpret_cast<const uint32_t*>(abase + k0 + 8 * ASTR + 8);
        const uint2* bbase = Bf + ks * 256 + lane;
#pragma unroll
        for (int nt = 0; nt < 8; nt++) {
            uint2 b = bbase[nt * 32];
            mma_f16(acc[nt], a0, a1, a2, a3, b.x, b.y);
        }
    }

    // Epilogue: c0,c1 -> (row, c2), (row, c2+1); c2,c3 -> row+8
    const int mr0 = row0 + warp * 16 + r;
    const int mr1 = mr0 + 8;
    const float dv0 = (mr0 < M) ? g_dinv[mr0] : 0.0f;
    const float dv1 = (mr1 < M) ? g_dinv[mr1] : 0.0f;

#pragma unroll
    for (int nt = 0; nt < 8; nt++) {
        const int col = nt * 8 + c2;
        const float2 bv = *reinterpret_cast<const float2*>(bias + col);
        if (mr0 < M) {
            const float hs0 = acc[nt][0] * dv0, hs1 = acc[nt][1] * dv0;
            __half2 hp = __floats2half2_rn(hs0, hs1);
            hout[(size_t)mr0 * (HID / 2) + (col >> 1)] = hp;
            *reinterpret_cast<float2*>(aout + (size_t)mr0 * HID + col) =
                make_float2(bv.x + hs0 * dv0, bv.y + hs1 * dv0);
        }
        if (mr1 < M) {
            const float hs2 = acc[nt][2] * dv1, hs3 = acc[nt][3] * dv1;
            __half2 hp = __floats2half2_rn(hs2, hs3);
            hout[(size_t)mr1 * (HID / 2) + (col >> 1)] = hp;
            *reinterpret_cast<float2*>(aout + (size_t)mr1 * HID + col) =
                make_float2(bv.x + hs2 * dv1, bv.y + hs3 * dv1);
        }
    }
}

// ---------------------------------------------------------------------------
// Pull-mode aggregation over CSR: out[d] += dinv[d] * sum_{s in N(d)} hh[s]
// 8 lanes per dst node; 16B fp16 gathers; two chains for MLP.
// ---------------------------------------------------------------------------
__device__ __forceinline__ void acc_16B(float2* acc, uint4 v) {
    float2 f0 = __half22float2(*reinterpret_cast<__half2*>(&v.x));
    float2 f1 = __half22float2(*reinterpret_cast<__half2*>(&v.y));
    float2 f2 = __half22float2(*reinterpret_cast<__half2*>(&v.z));
    float2 f3 = __half22float2(*reinterpret_cast<__half2*>(&v.w));
    acc[0].x += f0.x; acc[0].y += f0.y;
    acc[1].x += f1.x; acc[1].y += f1.y;
    acc[2].x += f2.x; acc[2].y += f2.y;
    acc[3].x += f3.x; acc[3].y += f3.y;
}

__global__ void __launch_bounds__(256) k_node_agg(const __half2* __restrict__ hh,
                                                  float* __restrict__ out,
                                                  int n)
{
    const int gid  = blockIdx.x * blockDim.x + threadIdx.x;
    const int node = gid >> 3;
    const int l    = gid & 7;
    if (node >= n) return;

    const int start = __ldg(&g_rowstart[node]);
    const int cn    = __ldg(&g_cnt[node]);
    const int half  = cn >> 1;

    float2 accA[4] = {{0,0},{0,0},{0,0},{0,0}};
    float2 accB[4] = {{0,0},{0,0},{0,0},{0,0}};

    const int a0 = start;
    const int b0 = start + half;
    for (int k = 0; k < half; k++) {
        const int sa = __ldg(&g_psrc[a0 + k]);
        const int sb = __ldg(&g_psrc[b0 + k]);
        const uint4 va = __ldg(reinterpret_cast<const uint4*>(hh + (size_t)sa * (HID / 2)) + l);
        const uint4 vb = __ldg(reinterpret_cast<const uint4*>(hh + (size_t)sb * (HID / 2)) + l);
        acc_16B(accA, va);
        acc_16B(accB, vb);
    }
    if (cn & 1) {
        const int s = __ldg(&g_psrc[start + cn - 1]);
        const uint4 v = __ldg(reinterpret_cast<const uint4*>(hh + (size_t)s * (HID / 2)) + l);
        acc_16B(accA, v);
    }

    const float dd = __ldg(&g_dinv[node]);
    float* p = out + (size_t)node * HID + l * 8;
    float4 o0 = *reinterpret_cast<float4*>(p);
    float4 o1 = *reinterpret_cast<float4*>(p + 4);
    o0.x += dd * (accA[0].x + accB[0].x);
    o0.y += dd * (accA[0].y + accB[0].y);
    o0.z += dd * (accA[1].x + accB[1].x);
    o0.w += dd * (accA[1].y + accB[1].y);
    o1.x += dd * (accA[2].x + accB[2].x);
    o1.y += dd * (accA[2].y + accB[2].y);
    o1.z += dd * (accA[3].x + accB[3].x);
    o1.w += dd * (accA[3].y + accB[3].y);
    *reinterpret_cast<float4*>(p)     = o0;
    *reinterpret_cast<float4*>(p + 4) = o1;
}

// ---------------------------------------------------------------------------
// Launch
// ---------------------------------------------------------------------------
extern "C" void kernel_launch(void* const* d_in, const int* in_sizes, int n_in,
                              void* d_out, int out_size)
{
    const float* x  = (const float*)d_in[0];
    const int*   ei = (const int*)d_in[1];   // edge_index is int32
    const float* W1 = (const float*)d_in[2];
    const float* b1 = (const float*)d_in[3];
    const float* W2 = (const float*)d_in[4];
    const float* b2 = (const float*)d_in[5];
    float* out = (float*)d_out;

    const int n  = in_sizes[0] / 128;
    const int nE = in_sizes[1] / 2;
    const int* src = ei;
    const int* dst = ei + nE;

    __half2* hh = nullptr;
    float* out1 = nullptr;
    uint2 *wf1 = nullptr, *wf2 = nullptr;
    cudaGetSymbolAddress((void**)&hh, g_hh);
    cudaGetSymbolAddress((void**)&out1, g_out1);
    cudaGetSymbolAddress((void**)&wf1, g_Wf1);
    cudaGetSymbolAddress((void**)&wf2, g_Wf2);

    const int nb_nodes = (n + 255) / 256;
    const int nb_edges = (nE + 255) / 256;
    const int nb_scan  = (n + 1023) / 1024;
    const int nb_agg   = (n * 8 + 255) / 256;
    const int nb_gemm  = (n + 127) / 128;

    const int smem1 = 128 * ASTR * 2 + 8 * 256 * (int)sizeof(uint2);  // 34816 + 16384
    const int smem2 = 128 * ASTR * 2 + 4 * 256 * (int)sizeof(uint2);  // 34816 + 8192
    cudaFuncSetAttribute(k_gemm_hmma<128, false>, cudaFuncAttributeMaxDynamicSharedMemorySize, smem1);
    cudaFuncSetAttribute(k_gemm_hmma<64, true>,   cudaFuncAttributeMaxDynamicSharedMemorySize, smem2);

    // W fragment packing (both layers, one launch)
    k_pack_w<<<12, 256>>>(W1, W2);

    // CSR build + dinv
    k_zero_cnt<<<nb_nodes, 256>>>(n);
    k_count<<<nb_edges, 256>>>(dst, nE);
    k_scan_block<<<nb_scan, 1024>>>(n);
    k_scan_finish<<<nb_nodes, 256>>>(n);
    k_scatter<<<nb_edges, 256>>>(src, dst, nE);

    // Layer 1
    k_gemm_hmma<128, false><<<nb_gemm, 256, smem1>>>(x, wf1, b1, hh, out1, n);
    k_node_agg<<<nb_agg, 256>>>(hh, out1, n);

    // Layer 2 (ReLU fused into A-load; init written straight to d_out)
    k_gemm_hmma<64, true><<<nb_gemm, 256, smem2>>>(out1, wf2, b2, hh, out, n);
    k_node_agg<<<nb_agg, 256>>>(hh, out, n);
}

// round 10
// speedup vs baseline: 1.3889x; 1.1059x over previous
#include <cuda_runtime.h>
#include <cuda_fp16.h>
#include <cstdint>

#define MAX_NODES 100000
#define MAX_EDGES 1250000
#define HID 64

// Scratch (allocation-free: __device__ globals)
__device__ int     g_cnt[MAX_NODES];
__device__ int     g_rowstart[MAX_NODES];
__device__ int     g_cursor[MAX_NODES];
__device__ int     g_blocksum[256];
__device__ float   g_dinv[MAX_NODES];
__device__ int     g_psrc[MAX_EDGES];
__device__ __half2 g_hh[(size_t)MAX_NODES * (HID / 2)];    // dinv[s]*h[s], fp16 gather table
__device__ __half2 g_out1h[(size_t)MAX_NODES * (HID / 2)]; // layer-1 output, fp16
__device__ uint2   g_Wf1[8 * 8 * 32];   // W1 fragments
__device__ uint2   g_Wf2[4 * 8 * 32];   // W2 fragments

// ---------------------------------------------------------------------------
// Fused: pack W fragments (idx < 3072) + zero g_cnt (idx < n)
// ---------------------------------------------------------------------------
__global__ void k_pack_zero(const float* __restrict__ W1, const float* __restrict__ W2, int n) {
    int idx = blockIdx.x * blockDim.x + threadIdx.x;
    if (idx < n) g_cnt[idx] = 0;
    if (idx < 3072) {
        const float* W;
        uint2* dstf;
        int rel;
        if (idx < 2048) { W = W1; dstf = g_Wf1; rel = idx; }
        else            { W = W2; dstf = g_Wf2; rel = idx - 2048; }
        const int lane  = rel & 31;
        const int nt    = (rel >> 5) & 7;
        const int kstep = rel >> 8;
        const int nn = nt * 8 + (lane >> 2);
        const int k0 = kstep * 16 + (lane & 3) * 2;
        __half2 b0 = __floats2half2_rn(__ldg(&W[(size_t)k0 * 64 + nn]),
                                       __ldg(&W[(size_t)(k0 + 1) * 64 + nn]));
        __half2 b1 = __floats2half2_rn(__ldg(&W[(size_t)(k0 + 8) * 64 + nn]),
                                       __ldg(&W[(size_t)(k0 + 9) * 64 + nn]));
        uint2 u;
        u.x = *reinterpret_cast<uint32_t*>(&b0);
        u.y = *reinterpret_cast<uint32_t*>(&b1);
        dstf[rel] = u;
    }
}

// ---------------------------------------------------------------------------
// CSR build: count -> block scan -> finish -> scatter
// ---------------------------------------------------------------------------
__global__ void k_count(const int* __restrict__ dst, int nE) {
    int e = blockIdx.x * blockDim.x + threadIdx.x;
    if (e < nE) atomicAdd(&g_cnt[__ldg(&dst[e])], 1);
}

__global__ void __launch_bounds__(1024) k_scan_block(int n) {
    __shared__ int sh[1024];
    const int t = threadIdx.x;
    const int i = blockIdx.x * 1024 + t;
    int v = (i < n) ? g_cnt[i] : 0;
    sh[t] = v;
    __syncthreads();
#pragma unroll
    for (int off = 1; off < 1024; off <<= 1) {
        int add = (t >= off) ? sh[t - off] : 0;
        __syncthreads();
        sh[t] += add;
        __syncthreads();
    }
    if (i < n) g_rowstart[i] = sh[t] - v;
    if (t == 1023) g_blocksum[blockIdx.x] = sh[t];
}

__global__ void __launch_bounds__(256) k_scan_finish(int n) {
    __shared__ int sh[128];
    const int t = threadIdx.x;
    const int seg = blockIdx.x >> 2;
    if (t < 128) sh[t] = (t < seg) ? g_blocksum[t] : 0;
    __syncthreads();
#pragma unroll
    for (int off = 64; off > 0; off >>= 1) {
        if (t < off) sh[t] += sh[t + off];
        __syncthreads();
    }
    const int base = sh[0];
    const int i = blockIdx.x * 256 + t;
    if (i < n) {
        int rs = g_rowstart[i] + base;
        g_rowstart[i] = rs;
        g_cursor[i]   = rs;
        g_dinv[i]     = rsqrtf((float)g_cnt[i] + 1.0f);
    }
}

__global__ void k_scatter(const int* __restrict__ src, const int* __restrict__ dst, int nE) {
    int e = blockIdx.x * blockDim.x + threadIdx.x;
    if (e < nE) {
        int d = __ldg(&dst[e]);
        int pos = atomicAdd(&g_cursor[d], 1);
        g_psrc[pos] = __ldg(&src[e]);
    }
}

// ---------------------------------------------------------------------------
// fp16 HMMA GEMM: h = act(A) @ W, mma.sync.m16n8k16 f32.f16.f16.f32.
// IN_HALF: A is fp16 (ReLU via __hmax2); else fp32.
// OUT_HALF: aout is fp16 (half2); else fp32.
// Epilogue: hh = fp16(h*dinv) ; aout = bias + (h*dinv)*dinv.
// ---------------------------------------------------------------------------
#define ASTR 136   // halves per A row in smem

__device__ __forceinline__ void mma_f16(float* c,
                                        uint32_t a0, uint32_t a1, uint32_t a2, uint32_t a3,
                                        uint32_t b0, uint32_t b1) {
    asm volatile("mma.sync.aligned.m16n8k16.row.col.f32.f16.f16.f32 "
                 "{%0,%1,%2,%3}, {%4,%5,%6,%7}, {%8,%9}, {%0,%1,%2,%3};"
                 : "+f"(c[0]), "+f"(c[1]), "+f"(c[2]), "+f"(c[3])
                 : "r"(a0), "r"(a1), "r"(a2), "r"(a3), "r"(b0), "r"(b1));
}

template<int KDIM, bool RELU_IN, bool IN_HALF, bool OUT_HALF>
__global__ void __launch_bounds__(256) k_gemm_hmma(const void* __restrict__ Ain,
                                                   const uint2* __restrict__ Wf,
                                                   const float* __restrict__ bias,
                                                   __half2* __restrict__ hout,
                                                   void* __restrict__ aout,
                                                   int M)
{
    extern __shared__ char smem[];
    __half* As = reinterpret_cast<__half*>(smem);                 // 128 x ASTR halves
    uint2*  Bf = reinterpret_cast<uint2*>(smem + 128 * ASTR * 2); // (KDIM/16)*256

    const int tid  = threadIdx.x;
    const int lane = tid & 31;
    const int warp = tid >> 5;
    const int row0 = blockIdx.x * 128;

    // B fragments -> smem
    for (int i = tid; i < (KDIM / 16) * 256; i += 256) Bf[i] = Wf[i];

    const int lrow = tid >> 1;
    const int arow = min(row0 + lrow, M - 1);
    if (!IN_HALF) {
        const float* A = (const float*)Ain;
        const int lc4 = (tid & 1) * 4;
#pragma unroll
        for (int k0 = 0; k0 < KDIM; k0 += 8) {
            float4 av = *reinterpret_cast<const float4*>(A + (size_t)arow * KDIM + k0 + lc4);
            if (RELU_IN) {
                av.x = fmaxf(av.x, 0.0f); av.y = fmaxf(av.y, 0.0f);
                av.z = fmaxf(av.z, 0.0f); av.w = fmaxf(av.w, 0.0f);
            }
            __half2 h0 = __floats2half2_rn(av.x, av.y);
            __half2 h1 = __floats2half2_rn(av.z, av.w);
            uint2 u;
            u.x = *reinterpret_cast<uint32_t*>(&h0);
            u.y = *reinterpret_cast<uint32_t*>(&h1);
            *reinterpret_cast<uint2*>(As + lrow * ASTR + k0 + lc4) = u;
        }
    } else {
        const __half* A = (const __half*)Ain;
        const int lch = (tid & 1) * (KDIM / 2);   // half of the row in halves
        const __half2 z2 = __float2half2_rn(0.0f);
#pragma unroll
        for (int k0 = 0; k0 < KDIM / 2; k0 += 8) {
            uint4 v = *reinterpret_cast<const uint4*>(A + (size_t)arow * KDIM + lch + k0);
            if (RELU_IN) {
                __half2* hv = reinterpret_cast<__half2*>(&v);
#pragma unroll
                for (int j = 0; j < 4; j++) hv[j] = __hmax2(hv[j], z2);
            }
            *reinterpret_cast<uint4*>(As + lrow * ASTR + lch + k0) = v;
        }
    }
    __syncthreads();

    float acc[8][4];
#pragma unroll
    for (int nt = 0; nt < 8; nt++)
#pragma unroll
        for (int j = 0; j < 4; j++) acc[nt][j] = 0.0f;

    const int r  = lane >> 2;
    const int c2 = (lane & 3) * 2;
    const __half* abase = As + (warp * 16 + r) * ASTR + c2;

#pragma unroll
    for (int ks = 0; ks < KDIM / 16; ks++) {
        const int k0 = ks * 16;
        uint32_t a0 = *reinterpret_cast<const uint32_t*>(abase + k0);
        uint32_t a1 = *reinterpret_cast<const uint32_t*>(abase + k0 + 8 * ASTR);
        uint32_t a2 = *reinterpret_cast<const uint32_t*>(abase + k0 + 8);
        uint32_t a3 = *reinterpret_cast<const uint32_t*>(abase + k0 + 8 * ASTR + 8);
        const uint2* bbase = Bf + ks * 256 + lane;
#pragma unroll
        for (int nt = 0; nt < 8; nt++) {
            uint2 b = bbase[nt * 32];
            mma_f16(acc[nt], a0, a1, a2, a3, b.x, b.y);
        }
    }

    const int mr0 = row0 + warp * 16 + r;
    const int mr1 = mr0 + 8;
    const float dv0 = (mr0 < M) ? g_dinv[mr0] : 0.0f;
    const float dv1 = (mr1 < M) ? g_dinv[mr1] : 0.0f;

#pragma unroll
    for (int nt = 0; nt < 8; nt++) {
        const int col = nt * 8 + c2;
        const float2 bv = *reinterpret_cast<const float2*>(bias + col);
        if (mr0 < M) {
            const float hs0 = acc[nt][0] * dv0, hs1 = acc[nt][1] * dv0;
            hout[(size_t)mr0 * (HID / 2) + (col >> 1)] = __floats2half2_rn(hs0, hs1);
            const float o0 = bv.x + hs0 * dv0, o1 = bv.y + hs1 * dv0;
            if (OUT_HALF)
                ((__half2*)aout)[(size_t)mr0 * (HID / 2) + (col >> 1)] = __floats2half2_rn(o0, o1);
            else
                *reinterpret_cast<float2*>((float*)aout + (size_t)mr0 * HID + col) = make_float2(o0, o1);
        }
        if (mr1 < M) {
            const float hs2 = acc[nt][2] * dv1, hs3 = acc[nt][3] * dv1;
            hout[(size_t)mr1 * (HID / 2) + (col >> 1)] = __floats2half2_rn(hs2, hs3);
            const float o2 = bv.x + hs2 * dv1, o3 = bv.y + hs3 * dv1;
            if (OUT_HALF)
                ((__half2*)aout)[(size_t)mr1 * (HID / 2) + (col >> 1)] = __floats2half2_rn(o2, o3);
            else
                *reinterpret_cast<float2*>((float*)aout + (size_t)mr1 * HID + col) = make_float2(o2, o3);
        }
    }
}

// ---------------------------------------------------------------------------
// Pull-mode aggregation: out[d] += dinv[d] * sum_{s in N(d)} hh[s]
// 8 lanes/node; 16B fp16 gathers; two chains. HALF_OUT selects out layout.
// ---------------------------------------------------------------------------
__device__ __forceinline__ void acc_16B(float2* acc, uint4 v) {
    float2 f0 = __half22float2(*reinterpret_cast<__half2*>(&v.x));
    float2 f1 = __half22float2(*reinterpret_cast<__half2*>(&v.y));
    float2 f2 = __half22float2(*reinterpret_cast<__half2*>(&v.z));
    float2 f3 = __half22float2(*reinterpret_cast<__half2*>(&v.w));
    acc[0].x += f0.x; acc[0].y += f0.y;
    acc[1].x += f1.x; acc[1].y += f1.y;
    acc[2].x += f2.x; acc[2].y += f2.y;
    acc[3].x += f3.x; acc[3].y += f3.y;
}

template<bool HALF_OUT>
__global__ void __launch_bounds__(256) k_node_agg(const __half2* __restrict__ hh,
                                                  void* __restrict__ out,
                                                  int n)
{
    const int gid  = blockIdx.x * blockDim.x + threadIdx.x;
    const int node = gid >> 3;
    const int l    = gid & 7;
    if (node >= n) return;

    const int start = __ldg(&g_rowstart[node]);
    const int cn    = __ldg(&g_cnt[node]);
    const int half  = cn >> 1;

    float2 accA[4] = {{0,0},{0,0},{0,0},{0,0}};
    float2 accB[4] = {{0,0},{0,0},{0,0},{0,0}};

    const int a0 = start;
    const int b0 = start + half;
    for (int k = 0; k < half; k++) {
        const int sa = __ldg(&g_psrc[a0 + k]);
        const int sb = __ldg(&g_psrc[b0 + k]);
        const uint4 va = __ldg(reinterpret_cast<const uint4*>(hh + (size_t)sa * (HID / 2)) + l);
        const uint4 vb = __ldg(reinterpret_cast<const uint4*>(hh + (size_t)sb * (HID / 2)) + l);
        acc_16B(accA, va);
        acc_16B(accB, vb);
    }
    if (cn & 1) {
        const int s = __ldg(&g_psrc[start + cn - 1]);
        const uint4 v = __ldg(reinterpret_cast<const uint4*>(hh + (size_t)s * (HID / 2)) + l);
        acc_16B(accA, v);
    }

    const float dd = __ldg(&g_dinv[node]);
    if (HALF_OUT) {
        uint4* p = reinterpret_cast<uint4*>((__half2*)out + (size_t)node * (HID / 2)) + l;
        uint4 o = *p;
        __half2* oh = reinterpret_cast<__half2*>(&o);
#pragma unroll
        for (int j = 0; j < 4; j++) {
            float2 f = __half22float2(oh[j]);
            f.x += dd * (accA[j].x + accB[j].x);
            f.y += dd * (accA[j].y + accB[j].y);
            oh[j] = __floats2half2_rn(f.x, f.y);
        }
        *p = o;
    } else {
        float* p = (float*)out + (size_t)node * HID + l * 8;
        float4 o0 = *reinterpret_cast<float4*>(p);
        float4 o1 = *reinterpret_cast<float4*>(p + 4);
        o0.x += dd * (accA[0].x + accB[0].x);
        o0.y += dd * (accA[0].y + accB[0].y);
        o0.z += dd * (accA[1].x + accB[1].x);
        o0.w += dd * (accA[1].y + accB[1].y);
        o1.x += dd * (accA[2].x + accB[2].x);
        o1.y += dd * (accA[2].y + accB[2].y);
        o1.z += dd * (accA[3].x + accB[3].x);
        o1.w += dd * (accA[3].y + accB[3].y);
        *reinterpret_cast<float4*>(p)     = o0;
        *reinterpret_cast<float4*>(p + 4) = o1;
    }
}

// ---------------------------------------------------------------------------
// Launch
// ---------------------------------------------------------------------------
extern "C" void kernel_launch(void* const* d_in, const int* in_sizes, int n_in,
                              void* d_out, int out_size)
{
    const float* x  = (const float*)d_in[0];
    const int*   ei = (const int*)d_in[1];   // edge_index is int32
    const float* W1 = (const float*)d_in[2];
    const float* b1 = (const float*)d_in[3];
    const float* W2 = (const float*)d_in[4];
    const float* b2 = (const float*)d_in[5];
    float* out = (float*)d_out;

    const int n  = in_sizes[0] / 128;
    const int nE = in_sizes[1] / 2;
    const int* src = ei;
    const int* dst = ei + nE;

    __half2 *hh = nullptr, *out1h = nullptr;
    uint2 *wf1 = nullptr, *wf2 = nullptr;
    cudaGetSymbolAddress((void**)&hh, g_hh);
    cudaGetSymbolAddress((void**)&out1h, g_out1h);
    cudaGetSymbolAddress((void**)&wf1, g_Wf1);
    cudaGetSymbolAddress((void**)&wf2, g_Wf2);

    const int nb_nodes = (n + 255) / 256;
    const int nb_edges = (nE + 255) / 256;
    const int nb_scan  = (n + 1023) / 1024;
    const int nb_agg   = (n * 8 + 255) / 256;
    const int nb_gemm  = (n + 127) / 128;

    const int smem1 = 128 * ASTR * 2 + 8 * 256 * (int)sizeof(uint2);  // 51200
    const int smem2 = 128 * ASTR * 2 + 4 * 256 * (int)sizeof(uint2);  // 43008
    cudaFuncSetAttribute(k_gemm_hmma<128, false, false, true>,
                         cudaFuncAttributeMaxDynamicSharedMemorySize, smem1);
    cudaFuncSetAttribute(k_gemm_hmma<64, true, true, false>,
                         cudaFuncAttributeMaxDynamicSharedMemorySize, smem2);

    // Fused W packing + cnt zeroing, then CSR build
    k_pack_zero<<<nb_nodes, 256>>>(W1, W2, n);
    k_count<<<nb_edges, 256>>>(dst, nE);
    k_scan_block<<<nb_scan, 1024>>>(n);
    k_scan_finish<<<nb_nodes, 256>>>(n);
    k_scatter<<<nb_edges, 256>>>(src, dst, nE);

    // Layer 1 (out1 in fp16)
    k_gemm_hmma<128, false, false, true><<<nb_gemm, 256, smem1>>>(x, wf1, b1, hh, out1h, n);
    k_node_agg<true><<<nb_agg, 256>>>(hh, out1h, n);

    // Layer 2 (fp16 A input, ReLU fused; fp32 output straight to d_out)
    k_gemm_hmma<64, true, true, false><<<nb_gemm, 256, smem2>>>(out1h, wf2, b2, hh, out, n);
    k_node_agg<false><<<nb_agg, 256>>>(hh, out, n);
}

// round 11
// speedup vs baseline: 1.4319x; 1.0309x over previous
#include <cuda_runtime.h>
#include <cuda_fp16.h>
#include <cstdint>

#define MAX_NODES 100000
#define MAX_EDGES 1250000
#define HID 64

// Scratch (allocation-free: __device__ globals)
__device__ int     g_cnt[MAX_NODES];
__device__ int     g_rowstart[MAX_NODES];
__device__ int     g_cursor[MAX_NODES];
__device__ int     g_total;
__device__ float   g_dinv[MAX_NODES];
__device__ int     g_psrc[MAX_EDGES];
__device__ __half2 g_hh[(size_t)MAX_NODES * (HID / 2)];    // dinv[s]*h[s], fp16 gather table
__device__ __half2 g_out1h[(size_t)MAX_NODES * (HID / 2)]; // layer-1 output, fp16
__device__ uint2   g_Wf1[8 * 8 * 32];   // W1 fragments
__device__ uint2   g_Wf2[4 * 8 * 32];   // W2 fragments

// ---------------------------------------------------------------------------
// Fused: pack W fragments (idx < 3072) + zero g_cnt (idx < n) + zero g_total
// ---------------------------------------------------------------------------
__global__ void k_pack_zero(const float* __restrict__ W1, const float* __restrict__ W2, int n) {
    int idx = blockIdx.x * blockDim.x + threadIdx.x;
    if (idx < n) g_cnt[idx] = 0;
    if (idx == 0) g_total = 0;
    if (idx < 3072) {
        const float* W;
        uint2* dstf;
        int rel;
        if (idx < 2048) { W = W1; dstf = g_Wf1; rel = idx; }
        else            { W = W2; dstf = g_Wf2; rel = idx - 2048; }
        const int lane  = rel & 31;
        const int nt    = (rel >> 5) & 7;
        const int kstep = rel >> 8;
        const int nn = nt * 8 + (lane >> 2);
        const int k0 = kstep * 16 + (lane & 3) * 2;
        __half2 b0 = __floats2half2_rn(__ldg(&W[(size_t)k0 * 64 + nn]),
                                       __ldg(&W[(size_t)(k0 + 1) * 64 + nn]));
        __half2 b1 = __floats2half2_rn(__ldg(&W[(size_t)(k0 + 8) * 64 + nn]),
                                       __ldg(&W[(size_t)(k0 + 9) * 64 + nn]));
        uint2 u;
        u.x = *reinterpret_cast<uint32_t*>(&b0);
        u.y = *reinterpret_cast<uint32_t*>(&b1);
        dstf[rel] = u;
    }
}

// ---------------------------------------------------------------------------
// CSR build: count -> rowstart (atomic bump allocator) -> scatter
// ---------------------------------------------------------------------------
__global__ void k_count(const int* __restrict__ dst, int nE) {
    int e = blockIdx.x * blockDim.x + threadIdx.x;
    if (e < nE) atomicAdd(&g_cnt[__ldg(&dst[e])], 1);
}

// Order-free row-start allocation: block-aggregated atomic bump.
// (Group order in g_psrc is schedule-dependent; aggregation only needs grouping.)
__global__ void __launch_bounds__(256) k_rowstart(int n) {
    __shared__ int wsum[8];
    __shared__ int sbase;
    const int tid  = threadIdx.x;
    const int lane = tid & 31;
    const int wid  = tid >> 5;
    const int i = blockIdx.x * 256 + tid;

    int c = (i < n) ? g_cnt[i] : 0;
    int scan = c;
#pragma unroll
    for (int off = 1; off < 32; off <<= 1) {
        int v = __shfl_up_sync(0xffffffffu, scan, off);
        if (lane >= off) scan += v;
    }
    if (lane == 31) wsum[wid] = scan;
    __syncthreads();
    if (wid == 0) {
        int w = (lane < 8) ? wsum[lane] : 0;
        int ws = w;
#pragma unroll
        for (int off = 1; off < 8; off <<= 1) {
            int v = __shfl_up_sync(0xffffffffu, ws, off);
            if (lane >= off) ws += v;
        }
        if (lane < 8) wsum[lane] = ws - w;            // exclusive warp offsets
        if (lane == 7) sbase = atomicAdd(&g_total, ws); // ws @lane7 = block total
    }
    __syncthreads();
    if (i < n) {
        const int rs = sbase + wsum[wid] + scan - c;
        g_rowstart[i] = rs;
        g_cursor[i]   = rs;
        g_dinv[i]     = rsqrtf((float)c + 1.0f);
    }
}

__global__ void k_scatter(const int* __restrict__ src, const int* __restrict__ dst, int nE) {
    int e = blockIdx.x * blockDim.x + threadIdx.x;
    if (e < nE) {
        int d = __ldg(&dst[e]);
        int pos = atomicAdd(&g_cursor[d], 1);
        g_psrc[pos] = __ldg(&src[e]);
    }
}

// ---------------------------------------------------------------------------
// fp16 HMMA GEMM: h = act(A) @ W, mma.sync.m16n8k16 f32.f16.f16.f32.
// IN_HALF: A is fp16 (ReLU via __hmax2); else fp32.
// OUT_HALF: aout is fp16 (half2); else fp32.
// Epilogue: hh = fp16(h*dinv) ; aout = bias + (h*dinv)*dinv.
// ---------------------------------------------------------------------------
#define ASTR 136   // halves per A row in smem

__device__ __forceinline__ void mma_f16(float* c,
                                        uint32_t a0, uint32_t a1, uint32_t a2, uint32_t a3,
                                        uint32_t b0, uint32_t b1) {
    asm volatile("mma.sync.aligned.m16n8k16.row.col.f32.f16.f16.f32 "
                 "{%0,%1,%2,%3}, {%4,%5,%6,%7}, {%8,%9}, {%0,%1,%2,%3};"
                 : "+f"(c[0]), "+f"(c[1]), "+f"(c[2]), "+f"(c[3])
                 : "r"(a0), "r"(a1), "r"(a2), "r"(a3), "r"(b0), "r"(b1));
}

template<int KDIM, bool RELU_IN, bool IN_HALF, bool OUT_HALF>
__global__ void __launch_bounds__(256) k_gemm_hmma(const void* __restrict__ Ain,
                                                   const uint2* __restrict__ Wf,
                                                   const float* __restrict__ bias,
                                                   __half2* __restrict__ hout,
                                                   void* __restrict__ aout,
                                                   int M)
{
    extern __shared__ char smem[];
    __half* As = reinterpret_cast<__half*>(smem);                 // 128 x ASTR halves
    uint2*  Bf = reinterpret_cast<uint2*>(smem + 128 * ASTR * 2); // (KDIM/16)*256

    const int tid  = threadIdx.x;
    const int lane = tid & 31;
    const int warp = tid >> 5;
    const int row0 = blockIdx.x * 128;

    // B fragments -> smem
    for (int i = tid; i < (KDIM / 16) * 256; i += 256) Bf[i] = Wf[i];

    const int lrow = tid >> 1;
    const int arow = min(row0 + lrow, M - 1);
    if (!IN_HALF) {
        const float* A = (const float*)Ain;
        const int lc4 = (tid & 1) * 4;
#pragma unroll
        for (int k0 = 0; k0 < KDIM; k0 += 8) {
            float4 av = *reinterpret_cast<const float4*>(A + (size_t)arow * KDIM + k0 + lc4);
            if (RELU_IN) {
                av.x = fmaxf(av.x, 0.0f); av.y = fmaxf(av.y, 0.0f);
                av.z = fmaxf(av.z, 0.0f); av.w = fmaxf(av.w, 0.0f);
            }
            __half2 h0 = __floats2half2_rn(av.x, av.y);
            __half2 h1 = __floats2half2_rn(av.z, av.w);
            uint2 u;
            u.x = *reinterpret_cast<uint32_t*>(&h0);
            u.y = *reinterpret_cast<uint32_t*>(&h1);
            *reinterpret_cast<uint2*>(As + lrow * ASTR + k0 + lc4) = u;
        }
    } else {
        const __half* A = (const __half*)Ain;
        const int lch = (tid & 1) * (KDIM / 2);
        const __half2 z2 = __float2half2_rn(0.0f);
#pragma unroll
        for (int k0 = 0; k0 < KDIM / 2; k0 += 8) {
            uint4 v = *reinterpret_cast<const uint4*>(A + (size_t)arow * KDIM + lch + k0);
            if (RELU_IN) {
                __half2* hv = reinterpret_cast<__half2*>(&v);
#pragma unroll
                for (int j = 0; j < 4; j++) hv[j] = __hmax2(hv[j], z2);
            }
            *reinterpret_cast<uint4*>(As + lrow * ASTR + lch + k0) = v;
        }
    }
    __syncthreads();

    float acc[8][4];
#pragma unroll
    for (int nt = 0; nt < 8; nt++)
#pragma unroll
        for (int j = 0; j < 4; j++) acc[nt][j] = 0.0f;

    const int r  = lane >> 2;
    const int c2 = (lane & 3) * 2;
    const __half* abase = As + (warp * 16 + r) * ASTR + c2;

#pragma unroll
    for (int ks = 0; ks < KDIM / 16; ks++) {
        const int k0 = ks * 16;
        uint32_t a0 = *reinterpret_cast<const uint32_t*>(abase + k0);
        uint32_t a1 = *reinterpret_cast<const uint32_t*>(abase + k0 + 8 * ASTR);
        uint32_t a2 = *reinterpret_cast<const uint32_t*>(abase + k0 + 8);
        uint32_t a3 = *reinterpret_cast<const uint32_t*>(abase + k0 + 8 * ASTR + 8);
        const uint2* bbase = Bf + ks * 256 + lane;
#pragma unroll
        for (int nt = 0; nt < 8; nt++) {
            uint2 b = bbase[nt * 32];
            mma_f16(acc[nt], a0, a1, a2, a3, b.x, b.y);
        }
    }

    const int mr0 = row0 + warp * 16 + r;
    const int mr1 = mr0 + 8;
    const float dv0 = (mr0 < M) ? g_dinv[mr0] : 0.0f;
    const float dv1 = (mr1 < M) ? g_dinv[mr1] : 0.0f;

#pragma unroll
    for (int nt = 0; nt < 8; nt++) {
        const int col = nt * 8 + c2;
        const float2 bv = *reinterpret_cast<const float2*>(bias + col);
        if (mr0 < M) {
            const float hs0 = acc[nt][0] * dv0, hs1 = acc[nt][1] * dv0;
            hout[(size_t)mr0 * (HID / 2) + (col >> 1)] = __floats2half2_rn(hs0, hs1);
            const float o0 = bv.x + hs0 * dv0, o1 = bv.y + hs1 * dv0;
            if (OUT_HALF)
                ((__half2*)aout)[(size_t)mr0 * (HID / 2) + (col >> 1)] = __floats2half2_rn(o0, o1);
            else
                *reinterpret_cast<float2*>((float*)aout + (size_t)mr0 * HID + col) = make_float2(o0, o1);
        }
        if (mr1 < M) {
            const float hs2 = acc[nt][2] * dv1, hs3 = acc[nt][3] * dv1;
            hout[(size_t)mr1 * (HID / 2) + (col >> 1)] = __floats2half2_rn(hs2, hs3);
            const float o2 = bv.x + hs2 * dv1, o3 = bv.y + hs3 * dv1;
            if (OUT_HALF)
                ((__half2*)aout)[(size_t)mr1 * (HID / 2) + (col >> 1)] = __floats2half2_rn(o2, o3);
            else
                *reinterpret_cast<float2*>((float*)aout + (size_t)mr1 * HID + col) = make_float2(o2, o3);
        }
    }
}

// ---------------------------------------------------------------------------
// Pull-mode aggregation: out[d] += dinv[d] * sum_{s in N(d)} hh[s]
// 8 lanes/node; 16B fp16 gathers; two chains. HALF_OUT selects out layout.
// ---------------------------------------------------------------------------
__device__ __forceinline__ void acc_16B(float2* acc, uint4 v) {
    float2 f0 = __half22float2(*reinterpret_cast<__half2*>(&v.x));
    float2 f1 = __half22float2(*reinterpret_cast<__half2*>(&v.y));
    float2 f2 = __half22float2(*reinterpret_cast<__half2*>(&v.z));
    float2 f3 = __half22float2(*reinterpret_cast<__half2*>(&v.w));
    acc[0].x += f0.x; acc[0].y += f0.y;
    acc[1].x += f1.x; acc[1].y += f1.y;
    acc[2].x += f2.x; acc[2].y += f2.y;
    acc[3].x += f3.x; acc[3].y += f3.y;
}

template<bool HALF_OUT>
__global__ void __launch_bounds__(256) k_node_agg(const __half2* __restrict__ hh,
                                                  void* __restrict__ out,
                                                  int n)
{
    const int gid  = blockIdx.x * blockDim.x + threadIdx.x;
    const int node = gid >> 3;
    const int l    = gid & 7;
    if (node >= n) return;

    const int start = __ldg(&g_rowstart[node]);
    const int cn    = __ldg(&g_cnt[node]);
    const int half  = cn >> 1;

    float2 accA[4] = {{0,0},{0,0},{0,0},{0,0}};
    float2 accB[4] = {{0,0},{0,0},{0,0},{0,0}};

    const int a0 = start;
    const int b0 = start + half;
    for (int k = 0; k < half; k++) {
        const int sa = __ldg(&g_psrc[a0 + k]);
        const int sb = __ldg(&g_psrc[b0 + k]);
        const uint4 va = __ldg(reinterpret_cast<const uint4*>(hh + (size_t)sa * (HID / 2)) + l);
        const uint4 vb = __ldg(reinterpret_cast<const uint4*>(hh + (size_t)sb * (HID / 2)) + l);
        acc_16B(accA, va);
        acc_16B(accB, vb);
    }
    if (cn & 1) {
        const int s = __ldg(&g_psrc[start + cn - 1]);
        const uint4 v = __ldg(reinterpret_cast<const uint4*>(hh + (size_t)s * (HID / 2)) + l);
        acc_16B(accA, v);
    }

    const float dd = __ldg(&g_dinv[node]);
    if (HALF_OUT) {
        uint4* p = reinterpret_cast<uint4*>((__half2*)out + (size_t)node * (HID / 2)) + l;
        uint4 o = *p;
        __half2* oh = reinterpret_cast<__half2*>(&o);
#pragma unroll
        for (int j = 0; j < 4; j++) {
            float2 f = __half22float2(oh[j]);
            f.x += dd * (accA[j].x + accB[j].x);
            f.y += dd * (accA[j].y + accB[j].y);
            oh[j] = __floats2half2_rn(f.x, f.y);
        }
        *p = o;
    } else {
        float* p = (float*)out + (size_t)node * HID + l * 8;
        float4 o0 = *reinterpret_cast<float4*>(p);
        float4 o1 = *reinterpret_cast<float4*>(p + 4);
        o0.x += dd * (accA[0].x + accB[0].x);
        o0.y += dd * (accA[0].y + accB[0].y);
        o0.z += dd * (accA[1].x + accB[1].x);
        o0.w += dd * (accA[1].y + accB[1].y);
        o1.x += dd * (accA[2].x + accB[2].x);
        o1.y += dd * (accA[2].y + accB[2].y);
        o1.z += dd * (accA[3].x + accB[3].x);
        o1.w += dd * (accA[3].y + accB[3].y);
        *reinterpret_cast<float4*>(p)     = o0;
        *reinterpret_cast<float4*>(p + 4) = o1;
    }
}

// ---------------------------------------------------------------------------
// Launch
// ---------------------------------------------------------------------------
extern "C" void kernel_launch(void* const* d_in, const int* in_sizes, int n_in,
                              void* d_out, int out_size)
{
    const float* x  = (const float*)d_in[0];
    const int*   ei = (const int*)d_in[1];   // edge_index is int32
    const float* W1 = (const float*)d_in[2];
    const float* b1 = (const float*)d_in[3];
    const float* W2 = (const float*)d_in[4];
    const float* b2 = (const float*)d_in[5];
    float* out = (float*)d_out;

    const int n  = in_sizes[0] / 128;
    const int nE = in_sizes[1] / 2;
    const int* src = ei;
    const int* dst = ei + nE;

    __half2 *hh = nullptr, *out1h = nullptr;
    uint2 *wf1 = nullptr, *wf2 = nullptr;
    cudaGetSymbolAddress((void**)&hh, g_hh);
    cudaGetSymbolAddress((void**)&out1h, g_out1h);
    cudaGetSymbolAddress((void**)&wf1, g_Wf1);
    cudaGetSymbolAddress((void**)&wf2, g_Wf2);

    const int nb_nodes = (n + 255) / 256;
    const int nb_edges = (nE + 255) / 256;
    const int nb_agg   = (n * 8 + 255) / 256;
    const int nb_gemm  = (n + 127) / 128;

    const int smem1 = 128 * ASTR * 2 + 8 * 256 * (int)sizeof(uint2);
    const int smem2 = 128 * ASTR * 2 + 4 * 256 * (int)sizeof(uint2);
    cudaFuncSetAttribute(k_gemm_hmma<128, false, false, true>,
                         cudaFuncAttributeMaxDynamicSharedMemorySize, smem1);
    cudaFuncSetAttribute(k_gemm_hmma<64, true, true, false>,
                         cudaFuncAttributeMaxDynamicSharedMemorySize, smem2);

    // Fused W packing + zeroing, then CSR build (count -> rowstart -> scatter)
    k_pack_zero<<<nb_nodes, 256>>>(W1, W2, n);
    k_count<<<nb_edges, 256>>>(dst, nE);
    k_rowstart<<<nb_nodes, 256>>>(n);
    k_scatter<<<nb_edges, 256>>>(src, dst, nE);

    // Layer 1 (out1 in fp16)
    k_gemm_hmma<128, false, false, true><<<nb_gemm, 256, smem1>>>(x, wf1, b1, hh, out1h, n);
    k_node_agg<true><<<nb_agg, 256>>>(hh, out1h, n);

    // Layer 2 (fp16 A input, ReLU fused; fp32 output straight to d_out)
    k_gemm_hmma<64, true, true, false><<<nb_gemm, 256, smem2>>>(out1h, wf2, b2, hh, out, n);
    k_node_agg<false><<<nb_agg, 256>>>(hh, out, n);
}